// round 4
// baseline (speedup 1.0000x reference)
#include <cuda_runtime.h>

#define NN 100000
#define NE 1600000
#define HID 64
#define NBLK 512
#define NTHR 256

// Scratch (no allocation allowed). Zero-initialized at module load; each
// launch restores the zero state of deg/acc/barrier counters itself, so the
// kernel is deterministic across graph replays.
__device__ float g_deg[NN];    // consumed + re-zeroed in phase 2
__device__ float g_acc[NN];    // consumed + re-zeroed in phase 4
__device__ float g_dinv[NN];
__device__ float g_px[NN];
__device__ float g_coef[5 * HID + 1];  // [az*.5 | (cz+lbz)*.5 | ah | ch+lbh | wout | bout]
__device__ unsigned g_ctr[3];
__device__ volatile unsigned g_flag[3];
__device__ unsigned g_dep[3];

__device__ __forceinline__ float tanh_approx(float x) {
    float y;
    asm("tanh.approx.f32 %0, %1;" : "=f"(y) : "f"(x));
    return y;
}

// Grid-wide barrier. Arrival: one atomic per block. Spin: VOLATILE PLAIN LOAD
// (no RMW — the R3 version spun with atomicAdd and convoyed the L2 atomic ALU).
// Self-resetting via departure counter so graph replays see clean state.
__device__ __forceinline__ void gbar(int id) {
    __syncthreads();
    if (threadIdx.x == 0) {
        __threadfence();  // publish this block's writes (also CCTL.IVALL)
        unsigned old = atomicAdd(&g_ctr[id], 1);
        if (old == NBLK - 1) {
            g_flag[id] = 1u;  // release (volatile store)
        } else {
            while (g_flag[id] == 0u) {}  // volatile ld spin — no atomics
        }
        unsigned d = atomicAdd(&g_dep[id], 1);
        if (d == NBLK - 1) {  // all blocks passed the spin: safe to reset
            g_ctr[id] = 0;
            g_flag[id] = 0;
            g_dep[id] = 0;
        }
        __threadfence();  // acquire side: order later loads after the spin
    }
    __syncthreads();
}

__global__ void __launch_bounds__(NTHR, 4)
fused_kernel(const float* __restrict__ x, const float* __restrict__ ew,
             const float* __restrict__ Wz, const float* __restrict__ bz,
             const float* __restrict__ Lz, const float* __restrict__ lbz,
             const float* __restrict__ Wh, const float* __restrict__ bh,
             const float* __restrict__ Lh, const float* __restrict__ lbh,
             const float* __restrict__ Wout, const float* __restrict__ bout,
             const int* __restrict__ src, const int* __restrict__ dst,
             float* __restrict__ out) {
    __shared__ float red[2][4];
    __shared__ float sc[5 * HID + 1];
    const int tid = threadIdx.x;
    const int gtid = blockIdx.x * NTHR + tid;
    const int gstride = NBLK * NTHR;

    // ---- Phase 1a: coefficient collapse (blocks 0..63, threads 0..63) ----
    // Z  = sigmoid(s*az + cz), Ht = tanh(s*ah + ch); sigmoid(u)=.5+.5*tanh(.5u)
    if (blockIdx.x < HID) {
        int h = blockIdx.x;
        if (tid < HID) {
            int warp = tid >> 5, lane = tid & 31;
            float lz = Lz[tid * HID + h];
            float lh = Lh[tid * HID + h];
            float az = Wz[tid] * lz;
            float cz = bz[tid] * lz;
            float ah = Wh[tid] * lh;
            float ch = bh[tid] * lh;
#pragma unroll
            for (int o = 16; o > 0; o >>= 1) {
                az += __shfl_down_sync(0xffffffffu, az, o);
                cz += __shfl_down_sync(0xffffffffu, cz, o);
                ah += __shfl_down_sync(0xffffffffu, ah, o);
                ch += __shfl_down_sync(0xffffffffu, ch, o);
            }
            if (lane == 0) {
                red[warp][0] = az;
                red[warp][1] = cz;
                red[warp][2] = ah;
                red[warp][3] = ch;
            }
        }
        __syncthreads();
        if (tid == 0) {
            int h2 = blockIdx.x;
            float az = red[0][0] + red[1][0];
            float cz = red[0][1] + red[1][1];
            float ah = red[0][2] + red[1][2];
            float ch = red[0][3] + red[1][3];
            g_coef[h2]           = 0.5f * az;
            g_coef[HID + h2]     = 0.5f * (cz + lbz[h2]);
            g_coef[2 * HID + h2] = ah;
            g_coef[3 * HID + h2] = ch + lbh[h2];
            g_coef[4 * HID + h2] = Wout[h2];
            if (h2 == 0) g_coef[5 * HID] = bout[0];
        }
    }

    // ---- Phase 1b: degree scatter (deg starts at 0; self-loop folded in P2) ----
    for (int i = gtid; i < NE / 4; i += gstride) {
        int4 d = ((const int4*)dst)[i];
        float4 w = ((const float4*)ew)[i];
        atomicAdd(&g_deg[d.x], w.x);
        atomicAdd(&g_deg[d.y], w.y);
        atomicAdd(&g_deg[d.z], w.z);
        atomicAdd(&g_deg[d.w], w.w);
    }

    gbar(0);

    // ---- Phase 2: dinv = rsqrt(deg+1); px = dinv*x; re-zero deg ----
    for (int i = gtid; i < NN; i += gstride) {
        float d = g_deg[i] + 1.0f;
        float r = (d > 0.f) ? rsqrtf(d) : 0.f;
        g_dinv[i] = r;
        g_px[i] = r * x[i];
        g_deg[i] = 0.f;
    }

    gbar(1);

    // ---- Phase 3: acc[dst] += px[src] * ew ----
    for (int i = gtid; i < NE / 4; i += gstride) {
        int4 s4 = ((const int4*)src)[i];
        int4 d4 = ((const int4*)dst)[i];
        float4 w = ((const float4*)ew)[i];
        atomicAdd(&g_acc[d4.x], g_px[s4.x] * w.x);
        atomicAdd(&g_acc[d4.y], g_px[s4.y] * w.y);
        atomicAdd(&g_acc[d4.z], g_px[s4.z] * w.z);
        atomicAdd(&g_acc[d4.w], g_px[s4.w] * w.w);
    }

    gbar(2);

    // ---- Phase 4: gate eval + output; re-zero acc for next replay ----
    for (int j = tid; j < 5 * HID + 1; j += NTHR) sc[j] = g_coef[j];
    __syncthreads();
    for (int i = gtid; i < NN; i += gstride) {
        float r = g_dinv[i];
        float s = r * (g_acc[i] + g_px[i]);  // px = dinv*x is the self-loop term
        g_acc[i] = 0.f;
        float o = sc[5 * HID];
#pragma unroll
        for (int h = 0; h < HID; h++) {
            float tz = tanh_approx(fmaf(s, sc[h], sc[HID + h]));
            float th = tanh_approx(fmaf(s, sc[2 * HID + h], sc[3 * HID + h]));
            float hn = (0.5f - 0.5f * tz) * th;  // (1-Z)*Ht
            o = fmaf(fmaxf(hn, 0.f), sc[4 * HID + h], o);
        }
        out[i] = o;
    }
}

extern "C" void kernel_launch(void* const* d_in, const int* in_sizes, int n_in,
                              void* d_out, int out_size) {
    const float* x    = (const float*)d_in[0];
    const float* ew   = (const float*)d_in[1];
    const float* Wz   = (const float*)d_in[2];
    const float* bz   = (const float*)d_in[3];
    const float* Lz   = (const float*)d_in[4];
    const float* lbz  = (const float*)d_in[5];
    // d_in[6..9]: Wr, br, Lr, lbr — mathematically dead (H0 == 0 -> H*R == 0)
    const float* Wh   = (const float*)d_in[10];
    const float* bh   = (const float*)d_in[11];
    const float* Lh   = (const float*)d_in[12];
    const float* lbh  = (const float*)d_in[13];
    const float* Wout = (const float*)d_in[14];
    const float* bout = (const float*)d_in[15];
    const int*   ei   = (const int*)d_in[16];
    float* out = (float*)d_out;

    fused_kernel<<<NBLK, NTHR>>>(x, ew, Wz, bz, Lz, lbz, Wh, bh, Lh, lbh,
                                 Wout, bout, ei, ei + NE, out);
}

// round 6
// speedup vs baseline: 3.0123x; 3.0123x over previous
#include <cuda_runtime.h>

#define NN 100000
#define NE 1600000
#define HID 64

// Scratch (no allocation allowed). Zero-initialized at module load; each
// consumer kernel re-zeroes what it reads, so deg/acc are back to zero by the
// end of every launch sequence -> graph replays are deterministic.
__device__ float g_deg[NN];   // zeroed again by k_dinv_coef after reading
__device__ float g_acc[NN];   // zeroed again by k_out after reading
__device__ float g_dinv[NN];
__device__ float g_px[NN];
__device__ float g_coef[5 * HID + 1];  // [az*.5 | (cz+lbz)*.5 | ah | ch+lbh | wout | bout]

#define NB_NODE ((NN + 255) / 256)       // 391 blocks of 256 for node loops
#define NB_EDGE ((NE / 4 + 255) / 256)   // 1563 blocks of 256 for edge loops

__device__ __forceinline__ float tanh_approx(float x) {
    float y;
    asm("tanh.approx.f32 %0, %1;" : "=f"(y) : "f"(x));
    return y;
}

// ---- K1: deg[dst] += ew (deg starts at 0; self-loop folded in K2) ----
__global__ void k_deg(const int* __restrict__ dst, const float* __restrict__ ew) {
    int i = blockIdx.x * blockDim.x + threadIdx.x;
    if (i < NE / 4) {
        int4 d = ((const int4*)dst)[i];
        float4 w = ((const float4*)ew)[i];
        atomicAdd(&g_deg[d.x], w.x);
        atomicAdd(&g_deg[d.y], w.y);
        atomicAdd(&g_deg[d.z], w.z);
        atomicAdd(&g_deg[d.w], w.w);
    }
}

// ---- K2: blocks [0, NB_NODE): dinv = rsqrt(deg+1); px = dinv*x; deg = 0.
//          blocks [NB_NODE, NB_NODE+HID): coefficient collapse.
// Z  = sigmoid(s*az + cz), Ht = tanh(s*ah + ch); sigmoid(u)=.5+.5*tanh(.5u),
// the 0.5 folded into the z-coefficients.
__global__ void k_dinv_coef(const float* __restrict__ x,
                            const float* __restrict__ Wz, const float* __restrict__ bz,
                            const float* __restrict__ Lz, const float* __restrict__ lbz,
                            const float* __restrict__ Wh, const float* __restrict__ bh,
                            const float* __restrict__ Lh, const float* __restrict__ lbh,
                            const float* __restrict__ Wout, const float* __restrict__ bout) {
    if (blockIdx.x < NB_NODE) {
        int i = blockIdx.x * blockDim.x + threadIdx.x;
        if (i < NN) {
            float d = g_deg[i] + 1.0f;   // +1 = self-loop weight
            float r = rsqrtf(d);          // d >= 1 always
            g_dinv[i] = r;
            g_px[i] = r * x[i];
            g_deg[i] = 0.f;               // clean for next replay
        }
        return;
    }
    // Coefficient blocks: one block per h, threads 0..63 reduce over j.
    __shared__ float red[2][4];
    int h = blockIdx.x - NB_NODE;
    int j = threadIdx.x;
    if (j < HID) {
        int warp = j >> 5, lane = j & 31;
        float lz = Lz[j * HID + h];
        float lh = Lh[j * HID + h];
        float az = Wz[j] * lz;
        float cz = bz[j] * lz;
        float ah = Wh[j] * lh;
        float ch = bh[j] * lh;
#pragma unroll
        for (int o = 16; o > 0; o >>= 1) {
            az += __shfl_down_sync(0xffffffffu, az, o);
            cz += __shfl_down_sync(0xffffffffu, cz, o);
            ah += __shfl_down_sync(0xffffffffu, ah, o);
            ch += __shfl_down_sync(0xffffffffu, ch, o);
        }
        if (lane == 0) {
            red[warp][0] = az;
            red[warp][1] = cz;
            red[warp][2] = ah;
            red[warp][3] = ch;
        }
    }
    __syncthreads();
    if (j == 0) {
        float az = red[0][0] + red[1][0];
        float cz = red[0][1] + red[1][1];
        float ah = red[0][2] + red[1][2];
        float ch = red[0][3] + red[1][3];
        g_coef[h]           = 0.5f * az;
        g_coef[HID + h]     = 0.5f * (cz + lbz[h]);
        g_coef[2 * HID + h] = ah;
        g_coef[3 * HID + h] = ch + lbh[h];
        g_coef[4 * HID + h] = Wout[h];
        if (h == 0) g_coef[5 * HID] = bout[0];
    }
}

// ---- K3: acc[dst] += px[src] * ew ----
__global__ void k_scatter(const int* __restrict__ src, const int* __restrict__ dst,
                          const float* __restrict__ ew) {
    int i = blockIdx.x * blockDim.x + threadIdx.x;
    if (i < NE / 4) {
        int4 s4 = ((const int4*)src)[i];
        int4 d4 = ((const int4*)dst)[i];
        float4 w = ((const float4*)ew)[i];
        atomicAdd(&g_acc[d4.x], g_px[s4.x] * w.x);
        atomicAdd(&g_acc[d4.y], g_px[s4.y] * w.y);
        atomicAdd(&g_acc[d4.z], g_px[s4.z] * w.z);
        atomicAdd(&g_acc[d4.w], g_px[s4.w] * w.w);
    }
}

// ---- K4: s = dinv*(acc + px); out = f(s); acc = 0 ----
// out = bout + sum_h relu( (0.5 - 0.5*tanh(az*s+cz)) * tanh(ah*s+ch) ) * wout[h]
__global__ void k_out(float* __restrict__ out) {
    __shared__ float sc[5 * HID + 1];
    int t = threadIdx.x;
    for (int j = t; j < 5 * HID + 1; j += blockDim.x) sc[j] = g_coef[j];
    __syncthreads();
    int i = blockIdx.x * blockDim.x + t;
    if (i < NN) {
        float r = g_dinv[i];
        float s = r * (g_acc[i] + g_px[i]);  // px = dinv*x is the self-loop term
        g_acc[i] = 0.f;                       // clean for next replay
        float o = sc[5 * HID];
#pragma unroll
        for (int h = 0; h < HID; h++) {
            float tz = tanh_approx(fmaf(s, sc[h], sc[HID + h]));
            float th = tanh_approx(fmaf(s, sc[2 * HID + h], sc[3 * HID + h]));
            float hn = (0.5f - 0.5f * tz) * th;  // (1-Z)*Ht
            o = fmaf(fmaxf(hn, 0.f), sc[4 * HID + h], o);
        }
        out[i] = o;
    }
}

extern "C" void kernel_launch(void* const* d_in, const int* in_sizes, int n_in,
                              void* d_out, int out_size) {
    const float* x    = (const float*)d_in[0];
    const float* ew   = (const float*)d_in[1];
    const float* Wz   = (const float*)d_in[2];
    const float* bz   = (const float*)d_in[3];
    const float* Lz   = (const float*)d_in[4];
    const float* lbz  = (const float*)d_in[5];
    // d_in[6..9]: Wr, br, Lr, lbr — mathematically dead (H0 == 0 -> H*R == 0)
    const float* Wh   = (const float*)d_in[10];
    const float* bh   = (const float*)d_in[11];
    const float* Lh   = (const float*)d_in[12];
    const float* lbh  = (const float*)d_in[13];
    const float* Wout = (const float*)d_in[14];
    const float* bout = (const float*)d_in[15];
    const int*   ei   = (const int*)d_in[16];
    const int*   src  = ei;
    const int*   dst  = ei + NE;
    float* out = (float*)d_out;

    const int TB = 256;
    k_deg<<<NB_EDGE, TB>>>(dst, ew);
    k_dinv_coef<<<NB_NODE + HID, TB>>>(x, Wz, bz, Lz, lbz, Wh, bh, Lh, lbh, Wout, bout);
    k_scatter<<<NB_EDGE, TB>>>(src, dst, ew);
    k_out<<<NB_NODE, TB>>>(out);
}

// round 7
// speedup vs baseline: 3.0828x; 1.0234x over previous
#include <cuda_runtime.h>

#define NN 100000
#define NE 1600000
#define HID 64

#define LUT_N 4096
#define LUT_R 4.0f
#define LUT_SCALE ((LUT_N - 1) / (2.0f * LUT_R))   // index = (s + R) * scale
#define LUT_STEP (2.0f * LUT_R / (LUT_N - 1))
#define LUT_BLKS (LUT_N / 256)

// Scratch (no allocation allowed). Zero-initialized at module load; each
// consumer kernel re-zeroes what it reads, so deg/acc are back to zero by the
// end of every launch sequence -> graph replays are deterministic.
__device__ float g_deg[NN];   // zeroed again by k_dinv_coef after reading
__device__ float g_acc[NN];   // zeroed again by k_out after reading
__device__ float g_dinv[NN];
__device__ float g_px[NN];
__device__ float g_coef[5 * HID + 1];  // [az*.5 | (cz+lbz)*.5 | ah | ch+lbh | wout | bout]
__device__ float2 g_lut[LUT_N];        // (f(s_i), f(s_{i+1})-f(s_i)) per interval

#define NB_NODE ((NN + 255) / 256)       // 391 blocks of 256 for node loops
#define NB_EDGE ((NE / 4 + 255) / 256)   // 1563 blocks of 256 for edge loops

__device__ __forceinline__ float tanh_approx(float x) {
    float y;
    asm("tanh.approx.f32 %0, %1;" : "=f"(y) : "f"(x));
    return y;
}

// Direct evaluation of the collapsed per-node scalar function:
// f(s) = bout + sum_h relu( (0.5 - 0.5*tanh(az*s+cz)) * tanh(ah*s+ch) ) * wout[h]
__device__ float eval_f(float s) {
    float o = g_coef[5 * HID];
#pragma unroll
    for (int h = 0; h < HID; h++) {
        float tz = tanh_approx(fmaf(s, g_coef[h], g_coef[HID + h]));
        float th = tanh_approx(fmaf(s, g_coef[2 * HID + h], g_coef[3 * HID + h]));
        float hn = (0.5f - 0.5f * tz) * th;  // (1-Z)*Ht
        o = fmaf(fmaxf(hn, 0.f), g_coef[4 * HID + h], o);
    }
    return o;
}

// ---- K1: deg[dst] += ew (deg starts at 0; self-loop folded in K2) ----
__global__ void k_deg(const int* __restrict__ dst, const float* __restrict__ ew) {
    int i = blockIdx.x * blockDim.x + threadIdx.x;
    if (i < NE / 4) {
        int4 d = ((const int4*)dst)[i];
        float4 w = ((const float4*)ew)[i];
        atomicAdd(&g_deg[d.x], w.x);
        atomicAdd(&g_deg[d.y], w.y);
        atomicAdd(&g_deg[d.z], w.z);
        atomicAdd(&g_deg[d.w], w.w);
    }
}

// ---- K2: blocks [0, NB_NODE): dinv = rsqrt(deg+1); px = dinv*x; deg = 0.
//          blocks [NB_NODE, NB_NODE+HID): coefficient collapse.
// Z  = sigmoid(s*az + cz), Ht = tanh(s*ah + ch); sigmoid(u)=.5+.5*tanh(.5u),
// the 0.5 folded into the z-coefficients.
__global__ void k_dinv_coef(const float* __restrict__ x,
                            const float* __restrict__ Wz, const float* __restrict__ bz,
                            const float* __restrict__ Lz, const float* __restrict__ lbz,
                            const float* __restrict__ Wh, const float* __restrict__ bh,
                            const float* __restrict__ Lh, const float* __restrict__ lbh,
                            const float* __restrict__ Wout, const float* __restrict__ bout) {
    if (blockIdx.x < NB_NODE) {
        int i = blockIdx.x * blockDim.x + threadIdx.x;
        if (i < NN) {
            float d = g_deg[i] + 1.0f;   // +1 = self-loop weight
            float r = rsqrtf(d);          // d >= 1 always
            g_dinv[i] = r;
            g_px[i] = r * x[i];
            g_deg[i] = 0.f;               // clean for next replay
        }
        return;
    }
    // Coefficient blocks: one block per h, threads 0..63 reduce over j.
    __shared__ float red[2][4];
    int h = blockIdx.x - NB_NODE;
    int j = threadIdx.x;
    if (j < HID) {
        int warp = j >> 5, lane = j & 31;
        float lz = Lz[j * HID + h];
        float lh = Lh[j * HID + h];
        float az = Wz[j] * lz;
        float cz = bz[j] * lz;
        float ah = Wh[j] * lh;
        float ch = bh[j] * lh;
#pragma unroll
        for (int o = 16; o > 0; o >>= 1) {
            az += __shfl_down_sync(0xffffffffu, az, o);
            cz += __shfl_down_sync(0xffffffffu, cz, o);
            ah += __shfl_down_sync(0xffffffffu, ah, o);
            ch += __shfl_down_sync(0xffffffffu, ch, o);
        }
        if (lane == 0) {
            red[warp][0] = az;
            red[warp][1] = cz;
            red[warp][2] = ah;
            red[warp][3] = ch;
        }
    }
    __syncthreads();
    if (j == 0) {
        float az = red[0][0] + red[1][0];
        float cz = red[0][1] + red[1][1];
        float ah = red[0][2] + red[1][2];
        float ch = red[0][3] + red[1][3];
        g_coef[h]           = 0.5f * az;
        g_coef[HID + h]     = 0.5f * (cz + lbz[h]);
        g_coef[2 * HID + h] = ah;
        g_coef[3 * HID + h] = ch + lbh[h];
        g_coef[4 * HID + h] = Wout[h];
        if (h == 0) g_coef[5 * HID] = bout[0];
    }
}

// ---- K3: blocks [0, NB_EDGE): acc[dst] += px[src] * ew
//          blocks [NB_EDGE, NB_EDGE+LUT_BLKS): build LUT of f over [-R, R].
// The LUT blocks depend only on g_coef (written by K2), not on the scatter.
__global__ void k_scatter(const int* __restrict__ src, const int* __restrict__ dst,
                          const float* __restrict__ ew) {
    if (blockIdx.x < NB_EDGE) {
        int i = blockIdx.x * blockDim.x + threadIdx.x;
        if (i < NE / 4) {
            int4 s4 = ((const int4*)src)[i];
            int4 d4 = ((const int4*)dst)[i];
            float4 w = ((const float4*)ew)[i];
            atomicAdd(&g_acc[d4.x], g_px[s4.x] * w.x);
            atomicAdd(&g_acc[d4.y], g_px[s4.y] * w.y);
            atomicAdd(&g_acc[d4.z], g_px[s4.z] * w.z);
            atomicAdd(&g_acc[d4.w], g_px[s4.w] * w.w);
        }
        return;
    }
    int e = (blockIdx.x - NB_EDGE) * blockDim.x + threadIdx.x;  // 0..LUT_N-1
    float s0 = -LUT_R + e * LUT_STEP;
    float f0 = eval_f(s0);
    float f1 = eval_f(s0 + LUT_STEP);
    g_lut[e] = make_float2(f0, f1 - f0);
}

// ---- K4: s = dinv*(acc + px); out = lerp-LUT f(s); acc = 0 ----
__global__ void k_out(float* __restrict__ out) {
    int i = blockIdx.x * blockDim.x + threadIdx.x;
    if (i < NN) {
        float r = g_dinv[i];
        float s = r * (g_acc[i] + g_px[i]);  // px = dinv*x is the self-loop term
        g_acc[i] = 0.f;                       // clean for next replay
        float o;
        float u = (s + LUT_R) * LUT_SCALE;
        if (u >= 0.0f && u < (float)(LUT_N - 1)) {
            float fl = floorf(u);
            float2 e = g_lut[(int)fl];
            o = fmaf(u - fl, e.y, e.x);       // linear interpolation
        } else {
            o = eval_f(s);                    // out-of-range fallback (rare/never)
        }
        out[i] = o;
    }
}

extern "C" void kernel_launch(void* const* d_in, const int* in_sizes, int n_in,
                              void* d_out, int out_size) {
    const float* x    = (const float*)d_in[0];
    const float* ew   = (const float*)d_in[1];
    const float* Wz   = (const float*)d_in[2];
    const float* bz   = (const float*)d_in[3];
    const float* Lz   = (const float*)d_in[4];
    const float* lbz  = (const float*)d_in[5];
    // d_in[6..9]: Wr, br, Lr, lbr — mathematically dead (H0 == 0 -> H*R == 0)
    const float* Wh   = (const float*)d_in[10];
    const float* bh   = (const float*)d_in[11];
    const float* Lh   = (const float*)d_in[12];
    const float* lbh  = (const float*)d_in[13];
    const float* Wout = (const float*)d_in[14];
    const float* bout = (const float*)d_in[15];
    const int*   ei   = (const int*)d_in[16];
    const int*   src  = ei;
    const int*   dst  = ei + NE;
    float* out = (float*)d_out;

    const int TB = 256;
    k_deg<<<NB_EDGE, TB>>>(dst, ew);
    k_dinv_coef<<<NB_NODE + HID, TB>>>(x, Wz, bz, Lz, lbz, Wh, bh, Lh, lbh, Wout, bout);
    k_scatter<<<NB_EDGE + LUT_BLKS, TB>>>(src, dst, ew);
    k_out<<<NB_NODE, TB>>>(out);
}